// round 9
// baseline (speedup 1.0000x reference)
#include <cuda_runtime.h>
#include <cuda_fp16.h>
#include <cstdint>
#include <math.h>

typedef unsigned long long ull;

#define FMA2(acc, a, b) asm("fma.rn.f32x2 %0, %1, %2, %0;" : "+l"(acc) : "l"(a), "l"(b))
#define PACK2(d, s)     asm("mov.b64 %0, {%1, %1};" : "=l"(d) : "f"(s))
#define UNPACK2(lo, hi, s) asm("mov.b64 {%0, %1}, %2;" : "=f"(lo), "=f"(hi) : "l"(s))
#define CP_ASYNC16(dst, src) \
    asm volatile("cp.async.cg.shared.global [%0], [%1], 16;" :: "r"(dst), "l"(src) : "memory")
#define CP_COMMIT()  asm volatile("cp.async.commit_group;" ::: "memory")
#define CP_WAIT0()   asm volatile("cp.async.wait_group 0;" ::: "memory")

constexpr int N    = 8192;
constexpr int FIN  = 512;
constexpr int FOUT = 128;
constexpr int NQ   = 512;    // k16 chunks
constexpr int NG   = 128;    // groups of 4 chunks (3 tensor + 1 cuda)

__device__ float g_h[N * FOUT];
__device__ uint2 g_hTb[NQ * 16 * 4 * 8];     // fp16 B fragments of h^T (2MB, L2-resident)
__device__ float g_E1[N], g_F1[N], g_E2[N], g_F2[N];

__device__ __forceinline__ uint32_t smem_u32(const void* p) {
    return (uint32_t)__cvta_generic_to_shared(p);
}
__device__ __forceinline__ uint32_t pack_h2(float lo, float hi) {
    uint32_t r;
    asm("cvt.rn.f16x2.f32 %0, %1, %2;" : "=r"(r) : "f"(hi), "f"(lo));
    return r;
}
__device__ __forceinline__ float2 h2f2(uint32_t u) {
    __half2 h = *reinterpret_cast<const __half2*>(&u);
    return __half22float2(h);
}

// m16n8k16 fp16 warp MMA, fp32 accumulate
__device__ __forceinline__ void mma16(float* c, uint32_t a0, uint32_t a1, uint32_t a2,
                                      uint32_t a3, uint32_t b0, uint32_t b1) {
    asm volatile(
        "mma.sync.aligned.m16n8k16.row.col.f32.f16.f16.f32 "
        "{%0,%1,%2,%3}, {%4,%5,%6,%7}, {%8,%9}, {%0,%1,%2,%3};"
        : "+f"(c[0]), "+f"(c[1]), "+f"(c[2]), "+f"(c[3])
        : "r"(a0), "r"(a1), "r"(a2), "r"(a3), "r"(b0), "r"(b1));
}

__device__ __forceinline__ float elu_f(float v) { return v > 0.f ? v : expm1f(v); }

// ---------------------------------------------------------------------------
// Kernel A: h = X @ W (fp32 FFMA2), BM=64. Emits g_h and fp16 B-fragment hT.
// ---------------------------------------------------------------------------
__global__ void __launch_bounds__(256) k_gemm_hw(const float* __restrict__ X,
                                                 const float* __restrict__ W) {
    __shared__ float sX[64][32];
    __shared__ float sB[32][FOUT];
    const int t = threadIdx.x;
    const int tx = t & 31, ty = t >> 5;
    const int m0 = blockIdx.x * 64;
    const int xr = t >> 2, xc0 = (t & 3) * 8;
    const int wr = t >> 3, wc0 = (t & 7) * 16;

    ull acc[8][2] = {};
    for (int kc = 0; kc < FIN / 32; ++kc) {
        const int k0 = kc * 32;
        __syncthreads();
        {
            float4*       dx = reinterpret_cast<float4*>(&sX[xr][xc0]);
            const float4* sx = reinterpret_cast<const float4*>(X + (size_t)(m0 + xr) * FIN + k0 + xc0);
            dx[0] = sx[0]; dx[1] = sx[1];
            float4*       dw = reinterpret_cast<float4*>(&sB[wr][wc0]);
            const float4* sw = reinterpret_cast<const float4*>(W + (size_t)(k0 + wr) * FOUT + wc0);
            dw[0] = sw[0]; dw[1] = sw[1]; dw[2] = sw[2]; dw[3] = sw[3];
        }
        __syncthreads();
        #pragma unroll 8
        for (int kk = 0; kk < 32; ++kk) {
            ulonglong2 b2 = *reinterpret_cast<const ulonglong2*>(&sB[kk][tx << 2]);
            #pragma unroll
            for (int k = 0; k < 8; ++k) {
                ull ap; PACK2(ap, sX[ty + 8 * k][kk]);
                FMA2(acc[k][0], ap, b2.x);
                FMA2(acc[k][1], ap, b2.y);
            }
        }
    }
    __half* hTb = reinterpret_cast<__half*>(g_hTb);
    #pragma unroll
    for (int k = 0; k < 8; ++k) {
        const int r = m0 + ty + 8 * k;
        float4 o;
        UNPACK2(o.x, o.y, acc[k][0]);
        UNPACK2(o.z, o.w, acc[k][1]);
        reinterpret_cast<float4*>(g_h + (size_t)r * FOUT)[tx] = o;
        const int q  = r >> 4;
        const int lc = (r >> 2) & 3;
        const int p  = r & 3;
        const float v[4] = {o.x, o.y, o.z, o.w};
        #pragma unroll
        for (int c = 0; c < 4; ++c) {
            const int f = tx * 4 + c;
            const int idx = (((q * 16 + (f >> 3)) * 4 + lc) * 8 + (f & 7)) * 4 + p;
            hTb[idx] = __float2half_rn(v[c]);
        }
    }
}

// ---------------------------------------------------------------------------
// Kernel B: E/F exp vectors
// ---------------------------------------------------------------------------
__global__ void __launch_bounds__(128) k_scores(const float* __restrict__ a) {
    const int i = blockIdx.x;
    const int t = threadIdx.x;
    const float hv = g_h[(size_t)i * FOUT + t];
    float p1 = hv * __ldg(&a[t]);
    float p2 = hv * __ldg(&a[FOUT + t]);
    #pragma unroll
    for (int off = 16; off; off >>= 1) {
        p1 += __shfl_xor_sync(0xffffffffu, p1, off);
        p2 += __shfl_xor_sync(0xffffffffu, p2, off);
    }
    __shared__ float r1[4], r2[4];
    const int w = t >> 5;
    if ((t & 31) == 0) { r1[w] = p1; r2[w] = p2; }
    __syncthreads();
    if (t == 0) {
        const float s1 = r1[0] + r1[1] + r1[2] + r1[3];
        const float s2 = r2[0] + r2[1] + r2[2] + r2[3];
        g_E1[i] = __expf(s1);  g_F1[i] = __expf(0.2f * s1);
        g_E2[i] = __expf(s2);  g_F2[i] = __expf(0.2f * s2);
    }
}

// ---------------------------------------------------------------------------
// Kernel C: hybrid tensor+CUDA masked-softmax aggregation.
// Groups of 4 chunks: q%4<3 -> fp16 mma.sync; q%4==3 -> fp32 FFMA into the
// SAME C-fragment registers. den on CUDA FADDs (warps 1,6) using rounded
// fragment values -> exact softmax cancellation.
// ---------------------------------------------------------------------------
__global__ void __launch_bounds__(256, 1) k_agg(const int* __restrict__ adj,
                                                float* __restrict__ out) {
    extern __shared__ float smem[];
    float* sEF = smem;                      // [0,8192)=E2, [8192,16384)=F2  (64KB)
    float* sH  = smem + 2 * N;              // 2 x 2048 floats (h chunk double buffer, 16KB)
    __shared__ uint32_t sBal[2][32];        // adj ballot words, double-buffered
    __shared__ float sDen[64];

    const int t = threadIdx.x;
    const int lane = t & 31, wid = t >> 5;
    const int mw = wid >> 2, nw = wid & 3;
    const int lr = lane >> 2, lc = lane & 3;
    const int i0 = blockIdx.x * 64;
    const bool do_den = (wid == 1) || (wid == 6);

    // stage E2/F2 tables
    {
        const float4* e4 = reinterpret_cast<const float4*>(g_E2);
        const float4* f4 = reinterpret_cast<const float4*>(g_F2);
        float4* s4 = reinterpret_cast<float4*>(sEF);
        for (int k = t; k < N / 4; k += 256) {
            s4[k]         = e4[k];
            s4[N / 4 + k] = f4[k];
        }
    }

    const int4* adj4 = reinterpret_cast<const int4*>(adj);

    // per-lane row data
    float e1[4], f1[4];
    const int4* arow[4];
    #pragma unroll
    for (int k = 0; k < 4; ++k) {
        const int row = i0 + mw * 32 + lr + 8 * k;
        e1[k] = g_E1[row];
        f1[k] = g_F1[row];
        arow[k] = adj4 + (size_t)row * (N / 4) + lc;
    }

    // cuda-chunk staging mappings
    const int crow = t >> 2, cseg = t & 3;                    // adj: thread -> (row, 16B seg)
    const int4* csrc_base = adj4 + (size_t)(i0 + crow) * (N / 4) + cseg;
    const uint32_t hdst0 = smem_u32(sH) + (uint32_t)t * 32;   // h: thread -> 32B

    // prologue: h stage (buffer 0, consumed by g=0) + adj regs for q=3
    int4 ac4 = __ldg(csrc_base + 3 * 4);
    CP_ASYNC16(hdst0,      (const char*)(g_h + 3 * 2048) + t * 32);
    CP_ASYNC16(hdst0 + 16, (const char*)(g_h + 3 * 2048) + t * 32 + 16);
    CP_COMMIT();

    // tensor prefetch for chunk 0
    int4 a4n[4];
    uint2 b2n[4];
    #pragma unroll
    for (int k = 0; k < 4; ++k) a4n[k] = __ldg(arow[k]);
    #pragma unroll
    for (int nt = 0; nt < 4; ++nt)
        b2n[nt] = __ldg(&g_hTb[((nw * 4 + nt) * 4 + lc) * 8 + lr]);

    float acc[2][4][4];
    #pragma unroll
    for (int mt = 0; mt < 2; ++mt)
        #pragma unroll
        for (int nt = 0; nt < 4; ++nt)
            #pragma unroll
            for (int r = 0; r < 4; ++r) acc[mt][nt][r] = 0.f;
    float dpT[4] = {0.f, 0.f, 0.f, 0.f};   // tensor-chunk den partials (per-lc slice)
    float dpC[4] = {0.f, 0.f, 0.f, 0.f};   // cuda-chunk den partials (full rows)

    const float4* sE4 = reinterpret_cast<const float4*>(sEF);
    const float4* sF4 = reinterpret_cast<const float4*>(sEF + N);

    #pragma unroll 1
    for (int g = 0; g < NG; ++g) {
        // ---- group start: cuda-chunk buffers ready ----
        CP_WAIT0();
        uint32_t bal[4];
        #pragma unroll
        for (int c = 0; c < 4; ++c) {
            const int v = (c == 0) ? ac4.x : (c == 1) ? ac4.y : (c == 2) ? ac4.z : ac4.w;
            bal[c] = __ballot_sync(0xffffffffu, v != 0);
        }
        if (lane < 4) sBal[g & 1][wid * 4 + lane] = bal[lane];
        __syncthreads();
        // stage next group's cuda chunk into the OTHER h buffer
        if (g + 1 < NG) {
            const int qc2 = 4 * g + 7;
            const uint32_t hdst = hdst0 + (uint32_t)(((g + 1) & 1) * 8192);
            ac4 = __ldg(csrc_base + qc2 * 4);
            CP_ASYNC16(hdst,      (const char*)(g_h + (size_t)qc2 * 2048) + t * 32);
            CP_ASYNC16(hdst + 16, (const char*)(g_h + (size_t)qc2 * 2048) + t * 32 + 16);
            CP_COMMIT();
        }

        // ---- 3 tensor chunks ----
        #pragma unroll
        for (int m = 0; m < 3; ++m) {
            const int q = 4 * g + m;
            int4 a4[4];
            uint2 b2[4];
            #pragma unroll
            for (int k = 0; k < 4; ++k) a4[k] = a4n[k];
            #pragma unroll
            for (int nt = 0; nt < 4; ++nt) b2[nt] = b2n[nt];
            // prefetch next tensor chunk (m<2 -> q+1; m==2 -> q+2)
            const int nq = (m < 2) ? q + 1 : q + 2;
            if (nq < NQ) {
                #pragma unroll
                for (int k = 0; k < 4; ++k) a4n[k] = __ldg(arow[k] + nq * 4);
                #pragma unroll
                for (int nt = 0; nt < 4; ++nt)
                    b2n[nt] = __ldg(&g_hTb[((nq * 16 + nw * 4 + nt) * 4 + lc) * 8 + lr]);
            }
            const float4 e4 = sE4[q * 4 + lc];
            const float4 f4 = sF4[q * 4 + lc];

            float w[4][4];
            #pragma unroll
            for (int k = 0; k < 4; ++k) {
                const float ek = e1[k], fk = f1[k];
                w[k][0] = a4[k].x ? fmaxf(ek * e4.x, fk * f4.x) : 0.f;
                w[k][1] = a4[k].y ? fmaxf(ek * e4.y, fk * f4.y) : 0.f;
                w[k][2] = a4[k].z ? fmaxf(ek * e4.z, fk * f4.z) : 0.f;
                w[k][3] = a4[k].w ? fmaxf(ek * e4.w, fk * f4.w) : 0.f;
            }

            #pragma unroll
            for (int mt = 0; mt < 2; ++mt) {
                const uint32_t af0 = pack_h2(w[2 * mt][0],     w[2 * mt][1]);
                const uint32_t af1 = pack_h2(w[2 * mt + 1][0], w[2 * mt + 1][1]);
                const uint32_t af2 = pack_h2(w[2 * mt][2],     w[2 * mt][3]);
                const uint32_t af3 = pack_h2(w[2 * mt + 1][2], w[2 * mt + 1][3]);
                #pragma unroll
                for (int nt = 0; nt < 4; ++nt)
                    mma16(acc[mt][nt], af0, af1, af2, af3, b2[nt].x, b2[nt].y);
                if (do_den) {   // den from the ROUNDED fragments -> exact cancel
                    const float2 q0 = h2f2(af0), q1 = h2f2(af1);
                    const float2 q2 = h2f2(af2), q3 = h2f2(af3);
                    dpT[2 * mt]     += (q0.x + q0.y) + (q2.x + q2.y);
                    dpT[2 * mt + 1] += (q1.x + q1.y) + (q3.x + q3.y);
                }
            }
        }

        // ---- 1 cuda chunk (q = 4g+3), fp32 FFMA into the same acc regs ----
        {
            const int qc = 4 * g + 3;
            const float2* hb = reinterpret_cast<const float2*>(sH + (g & 1) * 2048);
            uint32_t balw[4][4];
            #pragma unroll
            for (int k = 0; k < 4; ++k)
                #pragma unroll
                for (int c = 0; c < 4; ++c)
                    balw[k][c] = sBal[g & 1][(4 * mw + k) * 4 + c];
            float4 e4c[4], f4c[4];
            #pragma unroll
            for (int mq = 0; mq < 4; ++mq) {
                e4c[mq] = sE4[qc * 4 + mq];
                f4c[mq] = sF4[qc * 4 + mq];
            }
            #pragma unroll
            for (int j = 0; j < 16; ++j) {
                const int mq = j >> 2, cj = j & 3;
                const float E2j = (cj == 0) ? e4c[mq].x : (cj == 1) ? e4c[mq].y
                                  : (cj == 2) ? e4c[mq].z : e4c[mq].w;
                const float F2j = (cj == 0) ? f4c[mq].x : (cj == 1) ? f4c[mq].y
                                  : (cj == 2) ? f4c[mq].z : f4c[mq].w;
                float2 h2[4];
                #pragma unroll
                for (int nt = 0; nt < 4; ++nt)
                    h2[nt] = hb[j * 64 + nw * 16 + 4 * nt + lc];
                const int sh = lr * 4 + mq;
                #pragma unroll
                for (int k = 0; k < 4; ++k) {
                    const float wv = fmaxf(e1[k] * E2j, f1[k] * F2j);
                    const float wg = ((balw[k][cj] >> sh) & 1u) ? wv : 0.f;
                    if (do_den) dpC[k] += wg;
                    const int mt = k >> 1, hf = (k & 1) * 2;
                    #pragma unroll
                    for (int nt = 0; nt < 4; ++nt) {
                        acc[mt][nt][hf]     = fmaf(wg, h2[nt].x, acc[mt][nt][hf]);
                        acc[mt][nt][hf + 1] = fmaf(wg, h2[nt].y, acc[mt][nt][hf + 1]);
                    }
                }
            }
        }
    }

    // ---- denominators ----
    if (do_den) {
        #pragma unroll
        for (int k = 0; k < 4; ++k) {
            float v = dpT[k];
            v += __shfl_xor_sync(0xffffffffu, v, 1);
            v += __shfl_xor_sync(0xffffffffu, v, 2);
            if (lc == 0) sDen[mw * 32 + 8 * k + lr] = v + dpC[k];
        }
    }
    __syncthreads();

    // ---- normalize + elu + store ----
    #pragma unroll
    for (int mt = 0; mt < 2; ++mt) {
        const int r0 = mw * 32 + mt * 16 + lr;
        const float inv0 = 1.f / sDen[r0];
        const float inv1 = 1.f / sDen[r0 + 8];
        #pragma unroll
        for (int nt = 0; nt < 4; ++nt) {
            const int col = nw * 32 + nt * 8 + lc * 2;
            float2 v0, v1;
            v0.x = elu_f(acc[mt][nt][0] * inv0);
            v0.y = elu_f(acc[mt][nt][1] * inv0);
            v1.x = elu_f(acc[mt][nt][2] * inv1);
            v1.y = elu_f(acc[mt][nt][3] * inv1);
            *reinterpret_cast<float2*>(out + (size_t)(i0 + r0) * FOUT + col)     = v0;
            *reinterpret_cast<float2*>(out + (size_t)(i0 + r0 + 8) * FOUT + col) = v1;
        }
    }
}

// ---------------------------------------------------------------------------
extern "C" void kernel_launch(void* const* d_in, const int* in_sizes, int n_in,
                              void* d_out, int out_size) {
    const float* X   = (const float*)d_in[0];   // 8192 x 512
    const int*   adj = (const int*)  d_in[1];   // 8192 x 8192
    const float* W   = (const float*)d_in[2];   // 512 x 128
    const float* a   = (const float*)d_in[3];   // 256 x 1
    float*       out = (float*)d_out;           // 8192 x 128

    cudaFuncSetAttribute(k_agg, cudaFuncAttributeMaxDynamicSharedMemorySize, 81920);

    k_gemm_hw<<<N / 64, 256>>>(X, W);
    k_scores<<<N, 128>>>(a);
    k_agg<<<N / 64, 256, 81920>>>(adj, out);
}